// round 4
// baseline (speedup 1.0000x reference)
#include <cuda_runtime.h>
#include <cstdint>

// Word2DM loss, Gram identity: sims = sum_{a<=b} w_ab * Gt[a,b] * Gx[a,b].
// Rows grouped 5x4; 10 roles x 2 m-halves per sample (TPS=20).
// 3-slot cp.async staging ring (prefetch depth 2), ONE barrier per phase,
// all log-sigmoid reductions deferred to a single epilogue pass.

#define NDIM 20
#define ROWF 400
#define ROW4 100
#define SPB  16
#define TPS  20
#define TPB  (SPB * TPS)        // 320
#define GSTRIDE 84              // words per 4-row group (4*20 + 4 pad)
#define SSTRIDE 424             // words per sample tile (5*84 + 4 pad)

__global__ void w2dm_zero(float* out) { out[0] = 0.0f; }

__device__ __forceinline__ float red2(uint64_t v) {
    float lo, hi; asm("mov.b64 {%0,%1},%2;" : "=f"(lo), "=f"(hi) : "l"(v));
    return lo + hi;
}
__device__ __forceinline__ uint64_t ffma2(uint64_t a, uint64_t b, uint64_t c) {
    uint64_t r; asm("fma.rn.f32x2 %0,%1,%2,%3;" : "=l"(r) : "l"(a), "l"(b), "l"(c));
    return r;
}
__device__ __forceinline__ float dot5(const uint64_t* x, const uint64_t* y) {
    uint64_t acc = 0;
    #pragma unroll
    for (int q = 0; q < 5; q++) acc = ffma2(x[q], y[q], acc);
    return red2(acc);
}

__device__ __forceinline__ void cp16(float* smp, const float* g) {
    unsigned a = (unsigned)__cvta_generic_to_shared(smp);
    asm volatile("cp.async.cg.shared.global [%0], [%1], 16;" :: "r"(a), "l"(g));
}
#define CP_COMMIT()  asm volatile("cp.async.commit_group;")
#define CP_WAIT(N)   asm volatile("cp.async.wait_group %0;" :: "n"(N))

// Gather SPB rows of W into padded tile layout.
__device__ __forceinline__ void stage_rows(float* __restrict__ dst,
                                           const float* __restrict__ W,
                                           const int* __restrict__ idxp,
                                           int stride, int tid)
{
    #pragma unroll
    for (int i = tid; i < SPB * ROW4; i += TPB) {
        const int ss = i / ROW4;
        const int e4 = i % ROW4;
        const int n  = e4 / 5;
        const int j  = e4 % 5;
        const int idx = idxp[ss * stride];
        cp16(dst + ss * SSTRIDE + (n >> 2) * GSTRIDE + (n & 3) * 20 + j * 4,
             W + (size_t)idx * ROWF + e4 * 4);
    }
}

__global__ __launch_bounds__(TPB, 2) void w2dm_kernel(
    const float* __restrict__ Wt,
    const float* __restrict__ Wc,
    const int*   __restrict__ tgt,
    const int*   __restrict__ ctx,
    const int*   __restrict__ neg,
    float*       __restrict__ out,
    int batch, int kneg, float inv_batch)
{
    extern __shared__ float sm[];
    float* bufs    = sm;                              // 3 * SPB*SSTRIDE
    float* part    = sm + 3 * SPB * SSTRIDE;          // (kneg+1) * TPB
    float* termbuf = part + (kneg + 1) * TPB;         // SPB*(kneg+1)
    int*   sidx    = (int*)(termbuf + SPB * (kneg + 1));

    const int tid  = threadIdx.x;
    const int s    = tid / TPS;
    const int p    = tid % TPS;
    const int role = p >> 1;
    const int h    = p & 1;
    const int gown = role % 5;
    const int gfor = (role + 1 + (role >= 5 ? 1 : 0)) % 5;
    const int sample0 = blockIdx.x * SPB;
    const int nload = kneg + 2;        // Bt, ctx, negs

    const int ob  = gown * 42 + 5 * h;   // u64 offsets within a sample tile
    const int fb0 = gfor * 42 + 5 * h;

    // ---- preload gather indices (invalid samples -> row 0) ----
    for (int i = tid; i < SPB * (2 + kneg); i += TPB) {
        int v;
        if (i < SPB) {
            const int smp = sample0 + i;
            v = (smp < batch) ? tgt[smp] : 0;
        } else if (i < 2 * SPB) {
            const int smp = sample0 + (i - SPB);
            v = (smp < batch) ? ctx[smp] : 0;
        } else {
            const int q = i - 2 * SPB;
            const int smp = sample0 + q / kneg;
            v = (smp < batch) ? neg[(size_t)smp * kneg + (q % kneg)] : 0;
        }
        sidx[i] = v;
    }
    __syncthreads();

    // stage helper by load index: 0=Bt, 1=ctx, j>=2 -> neg col j-2
    auto stage_j = [&](int j) {
        float* dst = bufs + (j % 3) * SPB * SSTRIDE;
        if (j == 0)      stage_rows(dst, Wt, sidx, 1, tid);
        else if (j == 1) stage_rows(dst, Wc, sidx + SPB, 1, tid);
        else             stage_rows(dst, Wc, sidx + 2 * SPB + (j - 2), kneg, tid);
        CP_COMMIT();
    };

    // ---- prologue: stage tiles 0 and 1 ----
    stage_j(0);
    stage_j(1);

    uint64_t o[4][5];
    float gts[21];

    // ---- phases j=0..nload-1 (j=0 computes Gt; j>=1 accumulates part) ----
    for (int j = 0; j < nload; j++) {
        if (j + 1 < nload) { CP_WAIT(1); } else { CP_WAIT(0); }
        __syncthreads();               // tile j visible; slot (j+2)%3 free
        if (j + 2 < nload) stage_j(j + 2);

        const uint64_t* tb = (const uint64_t*)
            (bufs + (j % 3) * SPB * SSTRIDE + s * SSTRIDE);
        #pragma unroll
        for (int a = 0; a < 4; a++)
            #pragma unroll
            for (int q = 0; q < 5; q++) o[a][q] = tb[ob + a * 10 + q];

        if (j == 0) {
            // Gt: 21 weighted pair values (halves combined via shfl)
            #pragma unroll
            for (int fb = 0; fb < 4; fb++) {
                uint64_t f[5];
                #pragma unroll
                for (int q = 0; q < 5; q++) f[q] = tb[fb0 + fb * 10 + q];
                #pragma unroll
                for (int a = 0; a < 4; a++) gts[fb * 4 + a] = dot5(o[a], f);
            }
            if (role < 5) {
                gts[16] = dot5(o[0], o[0]); gts[17] = dot5(o[0], o[1]);
                gts[18] = dot5(o[0], o[2]); gts[19] = dot5(o[0], o[3]);
                gts[20] = dot5(o[1], o[1]);
            } else {
                gts[16] = dot5(o[1], o[2]); gts[17] = dot5(o[1], o[3]);
                gts[18] = dot5(o[2], o[2]); gts[19] = dot5(o[2], o[3]);
                gts[20] = dot5(o[3], o[3]);
            }
            #pragma unroll
            for (int i = 0; i < 16; i++) {
                float fu = gts[i] + __shfl_xor_sync(0xffffffffu, gts[i], 1);
                gts[i] = 2.0f * fu;
            }
            const bool A = (role < 5);
            const float wv[5] = { A ? 1.f : 2.f, 2.f, A ? 2.f : 1.f, 2.f, 1.f };
            #pragma unroll
            for (int i = 0; i < 5; i++) {
                float fu = gts[16 + i] + __shfl_xor_sync(0xffffffffu, gts[16 + i], 1);
                gts[16 + i] = wv[i] * fu;
            }
        } else {
            float acc = 0.0f;
            #pragma unroll
            for (int fb = 0; fb < 4; fb++) {
                uint64_t f[5];
                #pragma unroll
                for (int q = 0; q < 5; q++) f[q] = tb[fb0 + fb * 10 + q];
                #pragma unroll
                for (int a = 0; a < 4; a++)
                    acc = fmaf(dot5(o[a], f), gts[fb * 4 + a], acc);
            }
            if (role < 5) {
                acc = fmaf(dot5(o[0], o[0]), gts[16], acc);
                acc = fmaf(dot5(o[0], o[1]), gts[17], acc);
                acc = fmaf(dot5(o[0], o[2]), gts[18], acc);
                acc = fmaf(dot5(o[0], o[3]), gts[19], acc);
                acc = fmaf(dot5(o[1], o[1]), gts[20], acc);
            } else {
                acc = fmaf(dot5(o[1], o[2]), gts[16], acc);
                acc = fmaf(dot5(o[1], o[3]), gts[17], acc);
                acc = fmaf(dot5(o[2], o[2]), gts[18], acc);
                acc = fmaf(dot5(o[2], o[3]), gts[19], acc);
                acc = fmaf(dot5(o[3], o[3]), gts[20], acc);
            }
            part[(j - 1) * TPB + s * TPS + p] = acc;   // private slot, no sync
        }
    }

    // ---- epilogue: all reductions at once ----
    __syncthreads();
    const int nterm = kneg + 1;
    const int ntask = SPB * nterm;
    for (int t = tid; t < ntask; t += TPB) {
        const int ss = t / nterm;
        const int kk = t % nterm;
        float sims = 0.0f;
        const float* pr = part + kk * TPB + ss * TPS;
        #pragma unroll
        for (int i = 0; i < TPS; i++) sims += pr[i];
        termbuf[t] = ((sample0 + ss) < batch)
                   ? log1pf(expf(kk == 0 ? -sims : sims)) : 0.0f;
    }
    __syncthreads();
    if (tid < 32) {
        float v = 0.0f;
        for (int t = tid; t < ntask; t += 32) v += termbuf[t];
        #pragma unroll
        for (int off = 16; off > 0; off >>= 1)
            v += __shfl_xor_sync(0xffffffffu, v, off);
        if (tid == 0) atomicAdd(out, v * inv_batch);
    }
}

extern "C" void kernel_launch(void* const* d_in, const int* in_sizes, int n_in,
                              void* d_out, int out_size)
{
    const float* Wt  = (const float*)d_in[0];
    const float* Wc  = (const float*)d_in[1];
    const int*   tgt = (const int*)d_in[2];
    const int*   ctx = (const int*)d_in[3];
    const int*   neg = (const int*)d_in[4];
    float*       out = (float*)d_out;

    const int batch = in_sizes[2];
    const int kneg  = in_sizes[4] / batch;
    const float inv_batch = 1.0f / (float)batch;

    const int smem_bytes =
        (3 * SPB * SSTRIDE + (kneg + 1) * TPB + SPB * (kneg + 1)) * (int)sizeof(float)
        + SPB * (2 + kneg) * (int)sizeof(int);

    cudaFuncSetAttribute(w2dm_kernel,
                         cudaFuncAttributeMaxDynamicSharedMemorySize, smem_bytes);

    w2dm_zero<<<1, 1>>>(out);

    const int grid = (batch + SPB - 1) / SPB;
    w2dm_kernel<<<grid, TPB, smem_bytes>>>(Wt, Wc, tgt, ctx, neg, out,
                                           batch, kneg, inv_batch);
}

// round 5
// speedup vs baseline: 1.1120x; 1.1120x over previous
#include <cuda_runtime.h>
#include <cstdint>

// Word2DM loss, Gram identity: sims = sum_{a<=b} w_ab * Gt[a,b] * Gx[a,b].
// Rows grouped 5x4; 10 roles x 2 m-halves per sample (TPS=20).
// Packed f32x2 accumulation (one reduction per phase), 3-slot cp.async ring,
// one barrier per phase, deferred log-sigmoid epilogue. SPB=8 -> 4 CTAs/SM.

#define NDIM 20
#define ROWF 400
#define ROW4 100
#define SPB  8
#define TPS  20
#define TPB  (SPB * TPS)        // 160
#define GSTRIDE 84              // words per 4-row group (4*20 + 4 pad)
#define SSTRIDE 424             // words per sample tile (5*84 + 4 pad)

__global__ void w2dm_zero(float* out) { out[0] = 0.0f; }

__device__ __forceinline__ float red2(uint64_t v) {
    float lo, hi; asm("mov.b64 {%0,%1},%2;" : "=f"(lo), "=f"(hi) : "l"(v));
    return lo + hi;
}
__device__ __forceinline__ uint64_t pack2(float g) {
    uint64_t r; asm("mov.b64 %0,{%1,%1};" : "=l"(r) : "f"(g));
    return r;
}
__device__ __forceinline__ uint64_t ffma2(uint64_t a, uint64_t b, uint64_t c) {
    uint64_t r; asm("fma.rn.f32x2 %0,%1,%2,%3;" : "=l"(r) : "l"(a), "l"(b), "l"(c));
    return r;
}
// packed partial dot (no reduction)
__device__ __forceinline__ uint64_t dot5p(const uint64_t* x, const uint64_t* y) {
    uint64_t acc = 0;
    #pragma unroll
    for (int q = 0; q < 5; q++) acc = ffma2(x[q], y[q], acc);
    return acc;
}

__device__ __forceinline__ void cp16(float* smp, const float* g) {
    unsigned a = (unsigned)__cvta_generic_to_shared(smp);
    asm volatile("cp.async.cg.shared.global [%0], [%1], 16;" :: "r"(a), "l"(g));
}
#define CP_COMMIT()  asm volatile("cp.async.commit_group;")
#define CP_WAIT(N)   asm volatile("cp.async.wait_group %0;" :: "n"(N))

__device__ __forceinline__ void stage_rows(float* __restrict__ dst,
                                           const float* __restrict__ W,
                                           const int* __restrict__ idxp,
                                           int stride, int tid)
{
    #pragma unroll
    for (int i = tid; i < SPB * ROW4; i += TPB) {
        const int ss = i / ROW4;
        const int e4 = i % ROW4;
        const int n  = e4 / 5;
        const int j  = e4 % 5;
        const int idx = idxp[ss * stride];
        cp16(dst + ss * SSTRIDE + (n >> 2) * GSTRIDE + (n & 3) * 20 + j * 4,
             W + (size_t)idx * ROWF + e4 * 4);
    }
}

__global__ __launch_bounds__(TPB, 4) void w2dm_kernel(
    const float* __restrict__ Wt,
    const float* __restrict__ Wc,
    const int*   __restrict__ tgt,
    const int*   __restrict__ ctx,
    const int*   __restrict__ neg,
    float*       __restrict__ out,
    int batch, int kneg, float inv_batch)
{
    extern __shared__ float sm[];
    float* bufs    = sm;                              // 3 * SPB*SSTRIDE
    float* part    = sm + 3 * SPB * SSTRIDE;          // (kneg+1) * TPB
    float* termbuf = part + (kneg + 1) * TPB;         // SPB*(kneg+1)
    int*   sidx    = (int*)(termbuf + SPB * (kneg + 1));

    const int tid  = threadIdx.x;
    const int s    = tid / TPS;
    const int p    = tid % TPS;
    const int role = p >> 1;
    const int h    = p & 1;
    const int gown = role % 5;
    const int gfor = (role + 1 + (role >= 5 ? 1 : 0)) % 5;
    const int sample0 = blockIdx.x * SPB;
    const int nload = kneg + 2;

    const int ob  = gown * 42 + 5 * h;   // u64 offsets in a sample tile
    const int fb0 = gfor * 42 + 5 * h;

    // ---- preload gather indices ----
    for (int i = tid; i < SPB * (2 + kneg); i += TPB) {
        int v;
        if (i < SPB) {
            const int smp = sample0 + i;
            v = (smp < batch) ? tgt[smp] : 0;
        } else if (i < 2 * SPB) {
            const int smp = sample0 + (i - SPB);
            v = (smp < batch) ? ctx[smp] : 0;
        } else {
            const int q = i - 2 * SPB;
            const int smp = sample0 + q / kneg;
            v = (smp < batch) ? neg[(size_t)smp * kneg + (q % kneg)] : 0;
        }
        sidx[i] = v;
    }
    __syncthreads();

    auto stage_j = [&](int j) {
        float* dst = bufs + (j % 3) * SPB * SSTRIDE;
        if (j == 0)      stage_rows(dst, Wt, sidx, 1, tid);
        else if (j == 1) stage_rows(dst, Wc, sidx + SPB, 1, tid);
        else             stage_rows(dst, Wc, sidx + 2 * SPB + (j - 2), kneg, tid);
        CP_COMMIT();
    };

    stage_j(0);
    stage_j(1);

    uint64_t o[4][5];
    float gts[21];

    // ---- phase 0 (peeled): Gt ----
    {
        CP_WAIT(1);
        __syncthreads();
        stage_j(2);

        const uint64_t* tb = (const uint64_t*)(bufs + 0 + s * SSTRIDE);
        #pragma unroll
        for (int a = 0; a < 4; a++)
            #pragma unroll
            for (int q = 0; q < 5; q++) o[a][q] = tb[ob + a * 10 + q];

        #pragma unroll
        for (int fb = 0; fb < 4; fb++) {
            uint64_t f[5];
            #pragma unroll
            for (int q = 0; q < 5; q++) f[q] = tb[fb0 + fb * 10 + q];
            #pragma unroll
            for (int a = 0; a < 4; a++) gts[fb * 4 + a] = red2(dot5p(o[a], f));
        }
        if (role < 5) {
            gts[16] = red2(dot5p(o[0], o[0])); gts[17] = red2(dot5p(o[0], o[1]));
            gts[18] = red2(dot5p(o[0], o[2])); gts[19] = red2(dot5p(o[0], o[3]));
            gts[20] = red2(dot5p(o[1], o[1]));
        } else {
            gts[16] = red2(dot5p(o[1], o[2])); gts[17] = red2(dot5p(o[1], o[3]));
            gts[18] = red2(dot5p(o[2], o[2])); gts[19] = red2(dot5p(o[2], o[3]));
            gts[20] = red2(dot5p(o[3], o[3]));
        }
        #pragma unroll
        for (int i = 0; i < 16; i++) {
            float fu = gts[i] + __shfl_xor_sync(0xffffffffu, gts[i], 1);
            gts[i] = 2.0f * fu;
        }
        const bool A = (role < 5);
        const float wv[5] = { A ? 1.f : 2.f, 2.f, A ? 2.f : 1.f, 2.f, 1.f };
        #pragma unroll
        for (int i = 0; i < 5; i++) {
            float fu = gts[16 + i] + __shfl_xor_sync(0xffffffffu, gts[16 + i], 1);
            gts[16 + i] = wv[i] * fu;
        }
    }

    // ---- phases j=1..nload-1: packed accumulation ----
    for (int j = 1; j < nload; j++) {
        if (j + 1 < nload) { CP_WAIT(1); } else { CP_WAIT(0); }
        __syncthreads();
        if (j + 2 < nload) stage_j(j + 2);

        const uint64_t* tb = (const uint64_t*)
            (bufs + (j % 3) * SPB * SSTRIDE + s * SSTRIDE);
        #pragma unroll
        for (int a = 0; a < 4; a++)
            #pragma unroll
            for (int q = 0; q < 5; q++) o[a][q] = tb[ob + a * 10 + q];

        uint64_t acc0 = 0, acc1 = 0;   // two packed chains for ILP
        #pragma unroll
        for (int fb = 0; fb < 4; fb++) {
            uint64_t f[5];
            #pragma unroll
            for (int q = 0; q < 5; q++) f[q] = tb[fb0 + fb * 10 + q];
            #pragma unroll
            for (int a = 0; a < 4; a++) {
                uint64_t d = dot5p(o[a], f);
                if (a & 1) acc1 = ffma2(d, pack2(gts[fb * 4 + a]), acc1);
                else       acc0 = ffma2(d, pack2(gts[fb * 4 + a]), acc0);
            }
        }
        if (role < 5) {
            acc0 = ffma2(dot5p(o[0], o[0]), pack2(gts[16]), acc0);
            acc1 = ffma2(dot5p(o[0], o[1]), pack2(gts[17]), acc1);
            acc0 = ffma2(dot5p(o[0], o[2]), pack2(gts[18]), acc0);
            acc1 = ffma2(dot5p(o[0], o[3]), pack2(gts[19]), acc1);
            acc0 = ffma2(dot5p(o[1], o[1]), pack2(gts[20]), acc0);
        } else {
            acc0 = ffma2(dot5p(o[1], o[2]), pack2(gts[16]), acc0);
            acc1 = ffma2(dot5p(o[1], o[3]), pack2(gts[17]), acc1);
            acc0 = ffma2(dot5p(o[2], o[2]), pack2(gts[18]), acc0);
            acc1 = ffma2(dot5p(o[2], o[3]), pack2(gts[19]), acc1);
            acc0 = ffma2(dot5p(o[3], o[3]), pack2(gts[20]), acc0);
        }
        part[(j - 1) * TPB + s * TPS + p] = red2(acc0) + red2(acc1);
    }

    // ---- epilogue ----
    __syncthreads();
    const int nterm = kneg + 1;
    const int ntask = SPB * nterm;
    for (int t = tid; t < ntask; t += TPB) {
        const int ss = t / nterm;
        const int kk = t % nterm;
        float sims = 0.0f;
        const float* pr = part + kk * TPB + ss * TPS;
        #pragma unroll
        for (int i = 0; i < TPS; i++) sims += pr[i];
        termbuf[t] = ((sample0 + ss) < batch)
                   ? log1pf(expf(kk == 0 ? -sims : sims)) : 0.0f;
    }
    __syncthreads();
    if (tid < 32) {
        float v = 0.0f;
        for (int t = tid; t < ntask; t += 32) v += termbuf[t];
        #pragma unroll
        for (int off = 16; off > 0; off >>= 1)
            v += __shfl_xor_sync(0xffffffffu, v, off);
        if (tid == 0) atomicAdd(out, v * inv_batch);
    }
}

extern "C" void kernel_launch(void* const* d_in, const int* in_sizes, int n_in,
                              void* d_out, int out_size)
{
    const float* Wt  = (const float*)d_in[0];
    const float* Wc  = (const float*)d_in[1];
    const int*   tgt = (const int*)d_in[2];
    const int*   ctx = (const int*)d_in[3];
    const int*   neg = (const int*)d_in[4];
    float*       out = (float*)d_out;

    const int batch = in_sizes[2];
    const int kneg  = in_sizes[4] / batch;
    const float inv_batch = 1.0f / (float)batch;

    const int smem_bytes =
        (3 * SPB * SSTRIDE + (kneg + 1) * TPB + SPB * (kneg + 1)) * (int)sizeof(float)
        + SPB * (2 + kneg) * (int)sizeof(int);

    cudaFuncSetAttribute(w2dm_kernel,
                         cudaFuncAttributeMaxDynamicSharedMemorySize, smem_bytes);

    w2dm_zero<<<1, 1>>>(out);

    const int grid = (batch + SPB - 1) / SPB;
    w2dm_kernel<<<grid, TPB, smem_bytes>>>(Wt, Wc, tgt, ctx, neg, out,
                                           batch, kneg, inv_batch);
}